// round 9
// baseline (speedup 1.0000x reference)
#include <cuda_runtime.h>
#include <cuda_fp16.h>
#include <cstdint>

#define B_ 2048
#define T_ 128
#define C_ 256
#define H_ 64
#define NT 256

// ---- SMEM (bytes), 112KB/CTA, 2 CTAs/SM ----------------------------------
// proj: X fp16 [128][256] swizzled 512B rows = 64KB @0
//       W fp16 [3][64][128] swizzled 256B rows = 48KB @65536 (per k-chunk)
// attn overlay (inside X region, X dead after proj):
//       K @0, V @16384, Q @32768  ([128][64] fp16, 128B rows)
#define SM_X 0
#define SM_W 65536
#define SM_K 0
#define SM_V 16384
#define SM_Q 32768
#define SMEM_BYTES 114688

// W^T fp16, [3][64][256], produced once by prep kernel
__device__ __half g_Wt[3 * 64 * 256];

// ---- PTX helpers ----------------------------------------------------------
__device__ __forceinline__ uint32_t smem_u32(const void* p) {
    uint32_t a;
    asm("{ .reg .u64 t; cvta.to.shared.u64 t, %1; cvt.u32.u64 %0, t; }"
        : "=r"(a) : "l"(p));
    return a;
}
__device__ __forceinline__ void ldm4(uint32_t* r, uint32_t addr) {
    asm volatile("ldmatrix.sync.aligned.m8n8.x4.shared.b16 {%0,%1,%2,%3}, [%4];"
                 : "=r"(r[0]), "=r"(r[1]), "=r"(r[2]), "=r"(r[3]) : "r"(addr));
}
__device__ __forceinline__ void ldm4t(uint32_t* r, uint32_t addr) {
    asm volatile("ldmatrix.sync.aligned.m8n8.x4.trans.shared.b16 {%0,%1,%2,%3}, [%4];"
                 : "=r"(r[0]), "=r"(r[1]), "=r"(r[2]), "=r"(r[3]) : "r"(addr));
}
__device__ __forceinline__ void mma16816(float* d, const uint32_t* a,
                                         uint32_t b0, uint32_t b1) {
    asm("mma.sync.aligned.m16n8k16.row.col.f32.f16.f16.f32 "
        "{%0,%1,%2,%3}, {%4,%5,%6,%7}, {%8,%9}, {%0,%1,%2,%3};"
        : "+f"(d[0]), "+f"(d[1]), "+f"(d[2]), "+f"(d[3])
        : "r"(a[0]), "r"(a[1]), "r"(a[2]), "r"(a[3]), "r"(b0), "r"(b1));
}
__device__ __forceinline__ uint32_t pack_h2(float a, float b) {
    uint32_t r;
    asm("cvt.rn.f16x2.f32 %0, %1, %2;" : "=r"(r) : "f"(b), "f"(a));
    return r;
}
__device__ __forceinline__ float ex2(float x) {
    float r;
    asm("ex2.approx.f32 %0, %1;" : "=f"(r) : "f"(x));
    return r;
}
__device__ __forceinline__ void cp16(uint32_t sdst, const void* gsrc) {
    asm volatile("cp.async.cg.shared.global [%0], [%1], 16;"
                 :: "r"(sdst), "l"(gsrc));
}
#define CP_COMMIT() asm volatile("cp.async.commit_group;" ::: "memory")
#define CP_WAIT0()  asm volatile("cp.async.wait_group 0;" ::: "memory")
// swizzled 16B-chunk offset within a row (conflict-free ldmatrix)
#define SWC(chunk, row) ((((chunk) ^ ((row) & 7)) << 4))

// ---- prep kernel: W[c][h] fp32 -> W^T[h][c] fp16 --------------------------
__global__ void prep_w(const float* __restrict__ Wk,
                       const float* __restrict__ Wq,
                       const float* __restrict__ Wv)
{
    int idx = blockIdx.x * 256 + threadIdx.x;   // 49152 total
    int m = idx >> 14;
    int r = idx & 16383;
    int h = r >> 8, c = r & 255;
    const float* W = (m == 0) ? Wk : ((m == 1) ? Wq : Wv);
    g_Wt[idx] = __float2half_rn(W[c * 64 + h]);
}

// stage one k-chunk of all 3 W matrices via cp.async (12 x 16B per thread)
__device__ __forceinline__ void stage_w(char* sm, int tid, int chunk) {
    const __half* base = g_Wt;
#pragma unroll
    for (int t = 0; t < 12; t++) {
        int idx = tid + (t << 8);         // 3072 16B units
        int m = idx >> 10;
        int rem = idx & 1023;
        int h = rem >> 4, j = rem & 15;
        uint32_t dst = smem_u32(sm) + SM_W + m * 16384 + h * 256 + SWC(j, h);
        cp16(dst, base + m * 16384 + h * 256 + chunk * 128 + j * 8);
    }
    CP_COMMIT();
}

// ---- main kernel ----------------------------------------------------------
__global__ void __launch_bounds__(NT, 2)
head_mma(const float* __restrict__ x, float* __restrict__ out)
{
    extern __shared__ char sm[];
    const uint32_t smb = smem_u32(sm);
    const int tid = threadIdx.x, lane = tid & 31, wid = tid >> 5;
    const float* xb = x + (size_t)blockIdx.x * (T_ * C_);

    // ---- kick off W chunk0 loads, then stage X (overlapped) --------------
    stage_w(sm, tid, 0);

    // X [128][256] fp32 -> fp16 swizzled, 512B rows (float4 loads, STS.64)
#pragma unroll 8
    for (int it = 0; it < 32; it++) {
        int u = tid + (it << 8);          // float4 index, 8192 total
        int row = u >> 6, cp4 = u & 63;   // 64 float4 per row
        float4 v = *(const float4*)(xb + 4 * u);
        uint2 pk = make_uint2(pack_h2(v.x, v.y), pack_h2(v.z, v.w));
        uint32_t off = row * 512 + SWC(cp4 >> 1, row) + ((cp4 & 1) << 3);
        *(uint2*)(sm + SM_X + off) = pk;
    }
    CP_WAIT0();
    __syncthreads();

    // ================= Phase 1: QKV projections ============================
    float pacc[3][2][4][4];
#pragma unroll
    for (int m = 0; m < 3; m++)
#pragma unroll
        for (int mt = 0; mt < 2; mt++)
#pragma unroll
            for (int nt = 0; nt < 4; nt++)
#pragma unroll
                for (int i = 0; i < 4; i++) pacc[m][mt][nt][i] = 0.f;

    const int mr = (wid & 3) * 32;      // warp M-block (rows)
    const int nc = (wid >> 2) * 32;     // warp N-block (cols within matrix)

#pragma unroll
    for (int chunk = 0; chunk < 2; chunk++) {
        if (chunk == 1) {
            __syncthreads();            // chunk0 MMAs done -> W writable
            stage_w(sm, tid, 1);
            CP_WAIT0();
            __syncthreads();
        }
#pragma unroll 4
        for (int ks = 0; ks < 8; ks++) {
            int kcol = chunk * 8 + ks;  // 16-half k-block index (0..15)
            uint32_t ah[2][4];
#pragma unroll
            for (int mt = 0; mt < 2; mt++) {
                int ar = mr + 16 * mt + (lane & 15);
                ldm4(ah[mt], smb + SM_X + ar * 512
                             + SWC(2 * kcol + (lane >> 4), ar));
            }
#pragma unroll
            for (int m = 0; m < 3; m++) {
#pragma unroll
                for (int n16 = 0; n16 < 2; n16++) {
                    uint32_t bh[4];
                    int bn = nc + 16 * n16 + ((lane >> 3) & 1) * 8 + (lane & 7);
                    ldm4(bh, smb + SM_W + m * 16384 + bn * 256
                             + SWC(2 * ks + (lane >> 4), bn));
#pragma unroll
                    for (int mt = 0; mt < 2; mt++)
#pragma unroll
                        for (int j = 0; j < 2; j++)
                            mma16816(pacc[m][mt][2 * n16 + j],
                                     ah[mt], bh[j], bh[j + 2]);
                }
            }
        }
    }
    __syncthreads();   // proj MMAs done; overlay attn region onto X

    // ---- spill K/Q/V fp16 tiles [row][h]; Q pre-scaled by log2e/16 -------
#pragma unroll
    for (int m = 0; m < 3; m++) {
        uint32_t base = (m == 0) ? SM_K : ((m == 1) ? SM_Q : SM_V);
        float scale = (m == 1) ? 0.09016844f : 1.0f;   // 2^-4 * log2(e)
#pragma unroll
        for (int mt = 0; mt < 2; mt++)
#pragma unroll
            for (int nt = 0; nt < 4; nt++) {
                float* d = pacc[m][mt][nt];
                int sra = mr + 16 * mt + (lane >> 2), srb = sra + 8;
                int c = nc + 8 * nt + 2 * (lane & 3);
                uint32_t o0 = sra * 128 + SWC(c >> 3, sra) + ((c & 7) << 1);
                uint32_t o1 = srb * 128 + SWC(c >> 3, srb) + ((c & 7) << 1);
                *(uint32_t*)(sm + base + o0) = pack_h2(d[0] * scale, d[1] * scale);
                *(uint32_t*)(sm + base + o1) = pack_h2(d[2] * scale, d[3] * scale);
            }
    }
    __syncthreads();

    // ---- load Q fragments into registers ---------------------------------
    const int r16 = wid * 16;
    uint32_t qf[4][4];
#pragma unroll
    for (int ks = 0; ks < 4; ks++) {
        int ar = r16 + (lane & 15);
        ldm4(qf[ks], smb + SM_Q + ar * 128 + SWC(2 * ks + (lane >> 4), ar));
    }

    // ============ Phase 2: flash attention, exp2 domain, P in regs =========
    const int ra = r16 + (lane >> 2), rb = ra + 8;
    float m0 = -1e30f, m1 = -1e30f, l0 = 0.f, l1 = 0.f;
    float oacc[8][4];
#pragma unroll
    for (int nt = 0; nt < 8; nt++)
#pragma unroll
        for (int i = 0; i < 4; i++) oacc[nt][i] = 0.f;

    const int cmax = (wid < 4) ? 1 : 2;
    for (int c = 0; c < cmax; c++) {
        // ---- S chunk: rows [r16,r16+16) x cols [64c, 64c+64) ----
        float sacc[8][4];
#pragma unroll
        for (int nt = 0; nt < 8; nt++)
#pragma unroll
            for (int i = 0; i < 4; i++) sacc[nt][i] = 0.f;

#pragma unroll
        for (int ks = 0; ks < 4; ks++) {
#pragma unroll
            for (int n16 = 0; n16 < 4; n16++) {
                if (4 * c + n16 <= wid) {
                    int bn = 64 * c + 16 * n16
                           + ((lane >> 3) & 1) * 8 + (lane & 7);
                    uint32_t kh[4];
                    ldm4(kh, smb + SM_K + bn * 128
                             + SWC(2 * ks + (lane >> 4), bn));
#pragma unroll
                    for (int j = 0; j < 2; j++)
                        mma16816(sacc[2 * n16 + j], qf[ks], kh[j], kh[j + 2]);
                }
            }
        }

        // ---- causal mask + online softmax (exp2 domain, warp-local) ----
        float cm0 = -1e30f, cm1 = -1e30f;
#pragma unroll
        for (int nt = 0; nt < 8; nt++) {
            bool act = (4 * c + (nt >> 1)) <= wid;
            int s0 = 64 * c + 8 * nt + 2 * (lane & 3);
            float v0 = (act && s0 <= ra)     ? sacc[nt][0] : -1e30f;
            float v1 = (act && s0 + 1 <= ra) ? sacc[nt][1] : -1e30f;
            float v2 = (act && s0 <= rb)     ? sacc[nt][2] : -1e30f;
            float v3 = (act && s0 + 1 <= rb) ? sacc[nt][3] : -1e30f;
            sacc[nt][0] = v0; sacc[nt][1] = v1;
            sacc[nt][2] = v2; sacc[nt][3] = v3;
            cm0 = fmaxf(cm0, fmaxf(v0, v1));
            cm1 = fmaxf(cm1, fmaxf(v2, v3));
        }
        cm0 = fmaxf(cm0, __shfl_xor_sync(0xFFFFFFFFu, cm0, 1));
        cm0 = fmaxf(cm0, __shfl_xor_sync(0xFFFFFFFFu, cm0, 2));
        cm1 = fmaxf(cm1, __shfl_xor_sync(0xFFFFFFFFu, cm1, 1));
        cm1 = fmaxf(cm1, __shfl_xor_sync(0xFFFFFFFFu, cm1, 2));

        float mn0 = fmaxf(m0, cm0), mn1 = fmaxf(m1, cm1);
        // ex2(-huge) underflows to 0 — masked lanes need no select
        float a0 = ex2(m0 - mn0), a1 = ex2(m1 - mn1);
        float cs0 = 0.f, cs1 = 0.f;
#pragma unroll
        for (int nt = 0; nt < 8; nt++) {
            float e0 = ex2(sacc[nt][0] - mn0);
            float e1 = ex2(sacc[nt][1] - mn0);
            float e2 = ex2(sacc[nt][2] - mn1);
            float e3 = ex2(sacc[nt][3] - mn1);
            sacc[nt][0] = e0; sacc[nt][1] = e1;
            sacc[nt][2] = e2; sacc[nt][3] = e3;
            cs0 += e0 + e1;
            cs1 += e2 + e3;
        }
        cs0 += __shfl_xor_sync(0xFFFFFFFFu, cs0, 1);
        cs0 += __shfl_xor_sync(0xFFFFFFFFu, cs0, 2);
        cs1 += __shfl_xor_sync(0xFFFFFFFFu, cs1, 1);
        cs1 += __shfl_xor_sync(0xFFFFFFFFu, cs1, 2);
        l0 = l0 * a0 + cs0;
        l1 = l1 * a1 + cs1;
        m0 = mn0; m1 = mn1;

        // rescale running O
#pragma unroll
        for (int nt = 0; nt < 8; nt++) {
            oacc[nt][0] *= a0; oacc[nt][1] *= a0;
            oacc[nt][2] *= a1; oacc[nt][3] *= a1;
        }

        // ---- O += P_chunk @ V_chunk, P packed from sacc in registers ----
#pragma unroll
        for (int ks2 = 0; ks2 < 4; ks2++) {
            if (4 * c + ks2 <= wid) {
                uint32_t pa[4];
                pa[0] = pack_h2(sacc[2 * ks2][0], sacc[2 * ks2][1]);
                pa[1] = pack_h2(sacc[2 * ks2][2], sacc[2 * ks2][3]);
                pa[2] = pack_h2(sacc[2 * ks2 + 1][0], sacc[2 * ks2 + 1][1]);
                pa[3] = pack_h2(sacc[2 * ks2 + 1][2], sacc[2 * ks2 + 1][3]);
#pragma unroll
                for (int ntv = 0; ntv < 4; ntv++) {
                    int vr = 64 * c + 16 * ks2 + (lane & 15);
                    uint32_t vh[4];
                    ldm4t(vh, smb + SM_V + vr * 128
                              + SWC(2 * ntv + (lane >> 4), vr));
#pragma unroll
                    for (int j = 0; j < 2; j++)
                        mma16816(oacc[2 * ntv + j],
                                 pa, vh[2 * j], vh[2 * j + 1]);
                }
            }
        }
    }

    // ---- normalize + write out -------------------------------------------
    float inv0 = 1.f / l0, inv1 = 1.f / l1;
    float* ob = out + (size_t)blockIdx.x * (T_ * H_);
#pragma unroll
    for (int nt = 0; nt < 8; nt++) {
        int c0 = 8 * nt + 2 * (lane & 3);
        *(float2*)(ob + ra * 64 + c0) =
            make_float2(oacc[nt][0] * inv0, oacc[nt][1] * inv0);
        *(float2*)(ob + rb * 64 + c0) =
            make_float2(oacc[nt][2] * inv1, oacc[nt][3] * inv1);
    }
}

extern "C" void kernel_launch(void* const* d_in, const int* in_sizes, int n_in,
                              void* d_out, int out_size) {
    const float* x  = (const float*)d_in[0];
    const float* Wk = (const float*)d_in[1];
    const float* Wq = (const float*)d_in[2];
    const float* Wv = (const float*)d_in[3];
    float* out = (float*)d_out;

    prep_w<<<192, 256>>>(Wk, Wq, Wv);

    cudaFuncSetAttribute(head_mma,
                         cudaFuncAttributeMaxDynamicSharedMemorySize,
                         SMEM_BYTES);
    head_mma<<<B_, NT, SMEM_BYTES>>>(x, out);
}

// round 10
// speedup vs baseline: 1.0331x; 1.0331x over previous
#include <cuda_runtime.h>
#include <cuda_fp16.h>
#include <cstdint>

#define B_ 2048
#define T_ 128
#define C_ 256
#define H_ 64
#define NT 256

// ---- SMEM (bytes), 112KB/CTA, 2 CTAs/SM ----------------------------------
#define SM_X 0
#define SM_W 65536
#define SM_K 0
#define SM_V 16384
#define SM_Q 32768
#define SMEM_BYTES 114688

// W^T fp16, [3][64][256], produced once by prep kernel
__device__ __half g_Wt[3 * 64 * 256];

// ---- PTX helpers ----------------------------------------------------------
__device__ __forceinline__ uint32_t smem_u32(const void* p) {
    uint32_t a;
    asm("{ .reg .u64 t; cvta.to.shared.u64 t, %1; cvt.u32.u64 %0, t; }"
        : "=r"(a) : "l"(p));
    return a;
}
__device__ __forceinline__ void ldm4(uint32_t* r, uint32_t addr) {
    asm volatile("ldmatrix.sync.aligned.m8n8.x4.shared.b16 {%0,%1,%2,%3}, [%4];"
                 : "=r"(r[0]), "=r"(r[1]), "=r"(r[2]), "=r"(r[3]) : "r"(addr));
}
__device__ __forceinline__ void ldm4t(uint32_t* r, uint32_t addr) {
    asm volatile("ldmatrix.sync.aligned.m8n8.x4.trans.shared.b16 {%0,%1,%2,%3}, [%4];"
                 : "=r"(r[0]), "=r"(r[1]), "=r"(r[2]), "=r"(r[3]) : "r"(addr));
}
__device__ __forceinline__ void mma16816(float* d, const uint32_t* a,
                                         uint32_t b0, uint32_t b1) {
    asm("mma.sync.aligned.m16n8k16.row.col.f32.f16.f16.f32 "
        "{%0,%1,%2,%3}, {%4,%5,%6,%7}, {%8,%9}, {%0,%1,%2,%3};"
        : "+f"(d[0]), "+f"(d[1]), "+f"(d[2]), "+f"(d[3])
        : "r"(a[0]), "r"(a[1]), "r"(a[2]), "r"(a[3]), "r"(b0), "r"(b1));
}
__device__ __forceinline__ uint32_t pack_h2(float a, float b) {
    uint32_t r;
    asm("cvt.rn.f16x2.f32 %0, %1, %2;" : "=r"(r) : "f"(b), "f"(a));
    return r;
}
__device__ __forceinline__ float ex2(float x) {
    float r;
    asm("ex2.approx.f32 %0, %1;" : "=f"(r) : "f"(x));
    return r;
}
__device__ __forceinline__ void cp16(uint32_t sdst, const void* gsrc) {
    asm volatile("cp.async.cg.shared.global [%0], [%1], 16;"
                 :: "r"(sdst), "l"(gsrc));
}
#define CP_COMMIT() asm volatile("cp.async.commit_group;" ::: "memory")
#define CP_WAIT0()  asm volatile("cp.async.wait_group 0;" ::: "memory")
#define SWC(chunk, row) ((((chunk) ^ ((row) & 7)) << 4))

// ---- prep kernel: W[c][h] fp32 -> W^T[h][c] fp16 --------------------------
__global__ void prep_w(const float* __restrict__ Wk,
                       const float* __restrict__ Wq,
                       const float* __restrict__ Wv)
{
    int idx = blockIdx.x * 256 + threadIdx.x;   // 49152 total
    int m = idx >> 14;
    int r = idx & 16383;
    int h = r >> 8, c = r & 255;
    const float* W = (m == 0) ? Wk : ((m == 1) ? Wq : Wv);
    g_Wt[idx] = __float2half_rn(W[c * 64 + h]);
}

// stage one k-chunk of all 3 W matrices via cp.async (12 x 16B per thread)
__device__ __forceinline__ void stage_w(char* sm, int tid, int chunk) {
    const __half* base = g_Wt;
#pragma unroll
    for (int t = 0; t < 12; t++) {
        int idx = tid + (t << 8);         // 3072 16B units
        int m = idx >> 10;
        int rem = idx & 1023;
        int h = rem >> 4, j = rem & 15;
        uint32_t dst = smem_u32(sm) + SM_W + m * 16384 + h * 256 + SWC(j, h);
        cp16(dst, base + m * 16384 + h * 256 + chunk * 128 + j * 8);
    }
    CP_COMMIT();
}

// ---- main kernel ----------------------------------------------------------
__global__ void __launch_bounds__(NT, 2)
head_mma(const float* __restrict__ x, float* __restrict__ out)
{
    extern __shared__ char sm[];
    const uint32_t smb = smem_u32(sm);
    const int tid = threadIdx.x, lane = tid & 31, wid = tid >> 5;
    const float* xb = x + (size_t)blockIdx.x * (T_ * C_);

    // ---- kick off W chunk0 loads, then stage X (overlapped) --------------
    stage_w(sm, tid, 0);

    // X [128][256] fp32 -> fp16 swizzled, 512B rows (float4 loads, STS.64)
#pragma unroll 8
    for (int it = 0; it < 32; it++) {
        int u = tid + (it << 8);          // float4 index, 8192 total
        int row = u >> 6, cp4 = u & 63;
        float4 v = *(const float4*)(xb + 4 * u);
        uint2 pk = make_uint2(pack_h2(v.x, v.y), pack_h2(v.z, v.w));
        uint32_t off = row * 512 + SWC(cp4 >> 1, row) + ((cp4 & 1) << 3);
        *(uint2*)(sm + SM_X + off) = pk;
    }
    CP_WAIT0();
    __syncthreads();

    // ================= Phase 1: QKV projections ============================
    float pacc[3][2][4][4];
#pragma unroll
    for (int m = 0; m < 3; m++)
#pragma unroll
        for (int mt = 0; mt < 2; mt++)
#pragma unroll
            for (int nt = 0; nt < 4; nt++)
#pragma unroll
                for (int i = 0; i < 4; i++) pacc[m][mt][nt][i] = 0.f;

    const int mr = (wid & 3) * 32;      // warp M-block (rows)
    const int nc = (wid >> 2) * 32;     // warp N-block (cols within matrix)

#pragma unroll
    for (int chunk = 0; chunk < 2; chunk++) {
        if (chunk == 1) {
            __syncthreads();            // chunk0 MMAs done -> W writable
            stage_w(sm, tid, 1);
            CP_WAIT0();
            __syncthreads();
        }
#pragma unroll 4
        for (int ks = 0; ks < 8; ks++) {
            int kcol = chunk * 8 + ks;
            uint32_t ah[2][4];
#pragma unroll
            for (int mt = 0; mt < 2; mt++) {
                int ar = mr + 16 * mt + (lane & 15);
                ldm4(ah[mt], smb + SM_X + ar * 512
                             + SWC(2 * kcol + (lane >> 4), ar));
            }
#pragma unroll
            for (int m = 0; m < 3; m++) {
#pragma unroll
                for (int n16 = 0; n16 < 2; n16++) {
                    uint32_t bh[4];
                    int bn = nc + 16 * n16 + ((lane >> 3) & 1) * 8 + (lane & 7);
                    ldm4(bh, smb + SM_W + m * 16384 + bn * 256
                             + SWC(2 * ks + (lane >> 4), bn));
#pragma unroll
                    for (int mt = 0; mt < 2; mt++)
#pragma unroll
                        for (int j = 0; j < 2; j++)
                            mma16816(pacc[m][mt][2 * n16 + j],
                                     ah[mt], bh[j], bh[j + 2]);
                }
            }
        }
    }
    __syncthreads();   // proj MMAs done; overlay attn region onto X

    // ---- spill K/Q/V fp16 tiles [row][h]; Q pre-scaled by log2e/16 -------
#pragma unroll
    for (int m = 0; m < 3; m++) {
        uint32_t base = (m == 0) ? SM_K : ((m == 1) ? SM_Q : SM_V);
        float scale = (m == 1) ? 0.09016844f : 1.0f;   // 2^-4 * log2(e)
#pragma unroll
        for (int mt = 0; mt < 2; mt++)
#pragma unroll
            for (int nt = 0; nt < 4; nt++) {
                float* d = pacc[m][mt][nt];
                int sra = mr + 16 * mt + (lane >> 2), srb = sra + 8;
                int c = nc + 8 * nt + 2 * (lane & 3);
                uint32_t o0 = sra * 128 + SWC(c >> 3, sra) + ((c & 7) << 1);
                uint32_t o1 = srb * 128 + SWC(c >> 3, srb) + ((c & 7) << 1);
                *(uint32_t*)(sm + base + o0) = pack_h2(d[0] * scale, d[1] * scale);
                *(uint32_t*)(sm + base + o1) = pack_h2(d[2] * scale, d[3] * scale);
            }
    }
    __syncthreads();

    // ---- SMSP-balanced strip map: SMSP s gets strips s and 7-s -----------
    // warps 0..3 -> strips 0..3 ; warps 4..7 -> strips 7,6,5,4
    const int sw = (wid < 4) ? wid : (11 - wid);
    const int r16 = sw * 16;

    // ---- load Q fragments into registers ---------------------------------
    uint32_t qf[4][4];
#pragma unroll
    for (int ks = 0; ks < 4; ks++) {
        int ar = r16 + (lane & 15);
        ldm4(qf[ks], smb + SM_Q + ar * 128 + SWC(2 * ks + (lane >> 4), ar));
    }

    // ============ Phase 2: flash attention, exp2 domain, P in regs =========
    const int ra = r16 + (lane >> 2), rb = ra + 8;
    float m0 = -1e30f, m1 = -1e30f, l0 = 0.f, l1 = 0.f;
    float oacc[8][4];
#pragma unroll
    for (int nt = 0; nt < 8; nt++)
#pragma unroll
        for (int i = 0; i < 4; i++) oacc[nt][i] = 0.f;

    const int cmax = (sw < 4) ? 1 : 2;
    for (int c = 0; c < cmax; c++) {
        // ---- S chunk: rows [r16,r16+16) x cols [64c, 64c+64) ----
        float sacc[8][4];
#pragma unroll
        for (int nt = 0; nt < 8; nt++)
#pragma unroll
            for (int i = 0; i < 4; i++) sacc[nt][i] = 0.f;

#pragma unroll
        for (int ks = 0; ks < 4; ks++) {
#pragma unroll
            for (int n16 = 0; n16 < 4; n16++) {
                if (4 * c + n16 <= sw) {
                    int bn = 64 * c + 16 * n16
                           + ((lane >> 3) & 1) * 8 + (lane & 7);
                    uint32_t kh[4];
                    ldm4(kh, smb + SM_K + bn * 128
                             + SWC(2 * ks + (lane >> 4), bn));
#pragma unroll
                    for (int j = 0; j < 2; j++)
                        mma16816(sacc[2 * n16 + j], qf[ks], kh[j], kh[j + 2]);
                }
            }
        }

        // ---- causal mask + online softmax (exp2 domain, warp-local) ----
        float cm0 = -1e30f, cm1 = -1e30f;
        if (64 * c + 64 <= r16) {
            // fully below diagonal: no masking needed
#pragma unroll
            for (int nt = 0; nt < 8; nt++) {
                cm0 = fmaxf(cm0, fmaxf(sacc[nt][0], sacc[nt][1]));
                cm1 = fmaxf(cm1, fmaxf(sacc[nt][2], sacc[nt][3]));
            }
        } else {
#pragma unroll
            for (int nt = 0; nt < 8; nt++) {
                bool act = (4 * c + (nt >> 1)) <= sw;
                int s0 = 64 * c + 8 * nt + 2 * (lane & 3);
                float v0 = (act && s0 <= ra)     ? sacc[nt][0] : -1e30f;
                float v1 = (act && s0 + 1 <= ra) ? sacc[nt][1] : -1e30f;
                float v2 = (act && s0 <= rb)     ? sacc[nt][2] : -1e30f;
                float v3 = (act && s0 + 1 <= rb) ? sacc[nt][3] : -1e30f;
                sacc[nt][0] = v0; sacc[nt][1] = v1;
                sacc[nt][2] = v2; sacc[nt][3] = v3;
                cm0 = fmaxf(cm0, fmaxf(v0, v1));
                cm1 = fmaxf(cm1, fmaxf(v2, v3));
            }
        }
        cm0 = fmaxf(cm0, __shfl_xor_sync(0xFFFFFFFFu, cm0, 1));
        cm0 = fmaxf(cm0, __shfl_xor_sync(0xFFFFFFFFu, cm0, 2));
        cm1 = fmaxf(cm1, __shfl_xor_sync(0xFFFFFFFFu, cm1, 1));
        cm1 = fmaxf(cm1, __shfl_xor_sync(0xFFFFFFFFu, cm1, 2));

        float mn0 = fmaxf(m0, cm0), mn1 = fmaxf(m1, cm1);
        float a0 = ex2(m0 - mn0), a1 = ex2(m1 - mn1);
        float cs0 = 0.f, cs1 = 0.f;
#pragma unroll
        for (int nt = 0; nt < 8; nt++) {
            float e0 = ex2(sacc[nt][0] - mn0);
            float e1 = ex2(sacc[nt][1] - mn0);
            float e2 = ex2(sacc[nt][2] - mn1);
            float e3 = ex2(sacc[nt][3] - mn1);
            sacc[nt][0] = e0; sacc[nt][1] = e1;
            sacc[nt][2] = e2; sacc[nt][3] = e3;
            cs0 += e0 + e1;
            cs1 += e2 + e3;
        }
        cs0 += __shfl_xor_sync(0xFFFFFFFFu, cs0, 1);
        cs0 += __shfl_xor_sync(0xFFFFFFFFu, cs0, 2);
        cs1 += __shfl_xor_sync(0xFFFFFFFFu, cs1, 1);
        cs1 += __shfl_xor_sync(0xFFFFFFFFu, cs1, 2);
        l0 = l0 * a0 + cs0;
        l1 = l1 * a1 + cs1;
        m0 = mn0; m1 = mn1;

#pragma unroll
        for (int nt = 0; nt < 8; nt++) {
            oacc[nt][0] *= a0; oacc[nt][1] *= a0;
            oacc[nt][2] *= a1; oacc[nt][3] *= a1;
        }

        // ---- O += P_chunk @ V_chunk, P packed from sacc in registers ----
#pragma unroll
        for (int ks2 = 0; ks2 < 4; ks2++) {
            if (4 * c + ks2 <= sw) {
                uint32_t pa[4];
                pa[0] = pack_h2(sacc[2 * ks2][0], sacc[2 * ks2][1]);
                pa[1] = pack_h2(sacc[2 * ks2][2], sacc[2 * ks2][3]);
                pa[2] = pack_h2(sacc[2 * ks2 + 1][0], sacc[2 * ks2 + 1][1]);
                pa[3] = pack_h2(sacc[2 * ks2 + 1][2], sacc[2 * ks2 + 1][3]);
#pragma unroll
                for (int ntv = 0; ntv < 4; ntv++) {
                    int vr = 64 * c + 16 * ks2 + (lane & 15);
                    uint32_t vh[4];
                    ldm4t(vh, smb + SM_V + vr * 128
                              + SWC(2 * ntv + (lane >> 4), vr));
#pragma unroll
                    for (int j = 0; j < 2; j++)
                        mma16816(oacc[2 * ntv + j],
                                 pa, vh[2 * j], vh[2 * j + 1]);
                }
            }
        }
    }

    // ---- normalize + write out -------------------------------------------
    float inv0 = 1.f / l0, inv1 = 1.f / l1;
    float* ob = out + (size_t)blockIdx.x * (T_ * H_);
#pragma unroll
    for (int nt = 0; nt < 8; nt++) {
        int c0 = 8 * nt + 2 * (lane & 3);
        *(float2*)(ob + ra * 64 + c0) =
            make_float2(oacc[nt][0] * inv0, oacc[nt][1] * inv0);
        *(float2*)(ob + rb * 64 + c0) =
            make_float2(oacc[nt][2] * inv1, oacc[nt][3] * inv1);
    }
}

extern "C" void kernel_launch(void* const* d_in, const int* in_sizes, int n_in,
                              void* d_out, int out_size) {
    const float* x  = (const float*)d_in[0];
    const float* Wk = (const float*)d_in[1];
    const float* Wq = (const float*)d_in[2];
    const float* Wv = (const float*)d_in[3];
    float* out = (float*)d_out;

    prep_w<<<192, 256>>>(Wk, Wq, Wv);

    cudaFuncSetAttribute(head_mma,
                         cudaFuncAttributeMaxDynamicSharedMemorySize,
                         SMEM_BYTES);
    head_mma<<<B_, NT, SMEM_BYTES>>>(x, out);
}